// round 2
// baseline (speedup 1.0000x reference)
#include <cuda_runtime.h>
#include <math.h>

#define NB 32
#define SDIM 256
#define SS 65536            // SDIM*SDIM
#define TOT (NB*SS)

#define T_FOV 0.08748866352592401f   // tan(10/360*pi)
#define EPSV 1e-7f
#define ONE_M_EPS 0.99999990f        // float(1.0 - 1e-7)
#define INV_GAMMA 0.45454545454545453f
#define GAMMA_F 2.2f

// Scratch (no allocations allowed)
static __device__ float g_params[NB * 8];   // la, lb, spec_alpha, spec_strength, ldx, ldy, ldz
static __device__ float g_min_depth[NB];
static __device__ float g_shadow[TOT];
static __device__ float g_tmp[TOT];

// Normalized 1D Gaussian weights (ksize=7, sigma=2), separable form of the
// reference's outer(g,g)/sum 2D kernel.
__constant__ float GW[7] = {0.07015933f, 0.13107488f, 0.19071282f,
                            0.21610594f,
                            0.19071282f, 0.13107488f, 0.07015933f};

__global__ void params_kernel(const float* __restrict__ netL,
                              const float* __restrict__ light) {
    int b = threadIdx.x;
    if (b >= NB) return;
    float t0 = tanhf(netL[b * 6 + 0]);
    float t1 = tanhf(netL[b * 6 + 1]);
    float t2 = tanhf(netL[b * 6 + 2]);
    float t5 = tanhf(netL[b * 6 + 5]);
    const float t_alpha = 10.313708498984761f;   // sqrt(128) - 1
    float sa = (t0 * 0.5f + 0.5f) * t_alpha + 1.0f;
    float spec_alpha = sa * sa;
    float spec_strength = (t5 * 0.5f + 0.5f) * 0.5f;
    float la = t1 * 0.5f + 0.5f;
    float lb = t2 * 0.5f + 0.5f;
    float lx = light[b * 2 + 0];
    float ly = light[b * 2 + 1];
    float n = sqrtf(lx * lx + ly * ly + 1.0f);
    float* p = g_params + b * 8;
    p[0] = la;
    p[1] = lb;
    p[2] = spec_alpha;
    p[3] = spec_strength;
    p[4] = lx / n;
    p[5] = ly / n;
    p[6] = 1.0f / n;
}

__global__ void mindepth_kernel(const float* __restrict__ depth) {
    __shared__ float red[256];
    int b = blockIdx.x;
    const float* d = depth + b * SS;
    float m = 1e30f;
    for (int i = threadIdx.x; i < SS; i += 256) m = fminf(m, d[i]);
    red[threadIdx.x] = m;
    __syncthreads();
    for (int s = 128; s > 0; s >>= 1) {
        if (threadIdx.x < s) red[threadIdx.x] = fminf(red[threadIdx.x], red[threadIdx.x + s]);
        __syncthreads();
    }
    if (threadIdx.x == 0) g_min_depth[b] = red[0];
}

__global__ void shadow_kernel(const float* __restrict__ depth) {
    int idx = blockIdx.x * blockDim.x + threadIdx.x;
    if (idx >= TOT) return;
    int b = idx >> 16;
    int p = idx & (SS - 1);
    int i = p >> 8;
    int j = p & 255;

    const float* dimg = depth + b * SS;
    float d = __ldg(dimg + p);

    // c[k] = (-1 + k*(2/255)) * t  (matches jnp.linspace(-1,1,256)*t)
    float ci = __fmul_rn(__fadd_rn(__fmul_rn((float)i, 2.0f / 255.0f), -1.0f), T_FOV);
    float cj = __fmul_rn(__fadd_rn(__fmul_rn((float)j, 2.0f / 255.0f), -1.0f), T_FOV);

    // pos0 = (c[j]*d, c[i]*d, d); step = -light_d / S
    float px = cj * d, py = ci * d, pz = d;
    const float* prm = g_params + b * 8;
    float sx = -prm[4] * (1.0f / 256.0f);
    float sy = -prm[5] * (1.0f / 256.0f);
    float sz = -prm[6] * (1.0f / 256.0f);
    float minz = g_min_depth[b] - 1e-5f;   // safety margin vs bilinear rounding

    float sh = 0.0f;
    #pragma unroll 1
    for (int k = 0; k < SDIM; k++) {
        px += sx; py += sy; pz += sz;
        if (pz < minz) break;   // sampled >= min_depth >= pz forever (pz strictly decreasing)
        float gx = px / pz / T_FOV;
        float gy = py / pz / T_FOV;
        float x = (gx + 1.0f) * 128.0f - 0.5f;
        float y = (gy + 1.0f) * 128.0f - 0.5f;
        float x0f = floorf(x);
        float y0f = floorf(y);
        float wx = x - x0f;
        float wy = y - y0f;
        int x0 = (int)x0f;
        int y0 = (int)y0f;
        int x0i = min(max(x0, 0), 255);
        int x1i = min(max(x0 + 1, 0), 255);
        int y0i = min(max(y0, 0), 255);
        int y1i = min(max(y0 + 1, 0), 255);
        float v00 = __ldg(dimg + y0i * SDIM + x0i);
        float v01 = __ldg(dimg + y0i * SDIM + x1i);
        float v10 = __ldg(dimg + y1i * SDIM + x0i);
        float v11 = __ldg(dimg + y1i * SDIM + x1i);
        float sampled = v00 * (1.0f - wx) * (1.0f - wy)
                      + v01 * wx * (1.0f - wy)
                      + v10 * (1.0f - wx) * wy
                      + v11 * wx * wy;
        if (sampled < pz) { sh = 1.0f; break; }
    }
    g_shadow[idx] = sh;
}

__global__ void blurh_kernel() {
    int idx = blockIdx.x * blockDim.x + threadIdx.x;
    if (idx >= TOT) return;
    int j = idx & 255;
    int row_base = idx & ~255;
    float acc = 0.0f;
    #pragma unroll
    for (int dj = -3; dj <= 3; dj++) {
        int jj = j + dj;
        if (jj >= 0 && jj < SDIM) acc += GW[dj + 3] * g_shadow[row_base + jj];
    }
    g_tmp[idx] = acc;
}

__global__ void final_kernel(const float* __restrict__ netA,
                             const float* __restrict__ normal,
                             float* __restrict__ out) {
    int idx = blockIdx.x * blockDim.x + threadIdx.x;
    if (idx >= TOT) return;
    int b = idx >> 16;
    int p = idx & (SS - 1);
    int i = p >> 8;
    int j = p & 255;

    const float* prm = g_params + b * 8;
    float la = prm[0], lb = prm[1], spec_alpha = prm[2], spec_strength = prm[3];
    float ldx = prm[4], ldy = prm[5], ldz = prm[6];

    // Vertical blur (zero padding) -> shadow_s
    const float* tmp = g_tmp + b * SS;
    float ssum = 0.0f;
    #pragma unroll
    for (int dy = -3; dy <= 3; dy++) {
        int ii = i + dy;
        if (ii >= 0 && ii < SDIM) ssum += GW[dy + 3] * tmp[ii * SDIM + j];
    }
    float shadow_factor = fminf(fmaxf(1.0f - ssum, 0.1f), 1.0f);

    const float* nb = normal + b * 3 * SS;
    float nx = __ldg(nb + p);
    float ny = __ldg(nb + SS + p);
    float nz = __ldg(nb + 2 * SS + p);

    float cosb = nx * ldx + ny * ldy + nz * ldz;
    float diffuse = fmaxf(cosb, 0.0f);

    // view_d = (-x[j], -x[i], 1)/norm  via flipped linspace indexing
    float aj = __fmul_rn(__fadd_rn(__fmul_rn((float)(255 - j), 2.0f / 255.0f), -1.0f), T_FOV);
    float ai = __fmul_rn(__fadd_rn(__fmul_rn((float)(255 - i), 2.0f / 255.0f), -1.0f), T_FOV);
    float nrm = sqrtf(ai * ai + aj * aj + 1.0f);
    float vdx = aj / nrm, vdy = ai / nrm, vdz = 1.0f / nrm;

    float rdx = 2.0f * cosb * nx - ldx;
    float rdy = 2.0f * cosb * ny - ldy;
    float rdz = 2.0f * cosb * nz - ldz;

    float mask = (i >= 5 && i < SDIM - 5 && j >= 5 && j < SDIM - 5) ? 1.0f : 0.0f;
    float spec = fmaxf(vdx * rdx + vdy * rdy + vdz * rdz, 0.0f)
               * ((cosb > 0.0f) ? 1.0f : 0.0f) * mask;
    float specc = fminf(fmaxf(spec, EPSV), ONE_M_EPS);
    float spec_sh = __powf(specc, spec_alpha);

    float shading = la + lb * diffuse * shadow_factor;
    float term2 = spec_strength * lb * spec_sh;

    const float* ab = netA + b * 5 * SS;
    float* ob = out + b * 3 * SS;
    #pragma unroll
    for (int c = 0; c < 3; c++) {
        float a = tanhf(__ldg(ab + c * SS + p));
        float alb = __powf(a * 0.5f + 0.5f, GAMMA_F);
        float r = alb * shading + term2;
        ob[c * SS + p] = __powf(fmaxf(r, EPSV), INV_GAMMA);
    }
}

extern "C" void kernel_launch(void* const* d_in, const int* in_sizes, int n_in,
                              void* d_out, int out_size) {
    const float* netA   = (const float*)d_in[0];
    const float* netL   = (const float*)d_in[1];
    const float* normal = (const float*)d_in[2];
    const float* depth  = (const float*)d_in[3];
    const float* light  = (const float*)d_in[4];
    float* out = (float*)d_out;

    params_kernel<<<1, 32>>>(netL, light);
    mindepth_kernel<<<NB, 256>>>(depth);
    shadow_kernel<<<TOT / 256, 256>>>(depth);
    blurh_kernel<<<TOT / 256, 256>>>();
    final_kernel<<<TOT / 256, 256>>>(netA, normal, out);
}

// round 5
// speedup vs baseline: 1.3469x; 1.3469x over previous
#include <cuda_runtime.h>
#include <math.h>

#define NB 32
#define SDIM 256
#define SS 65536            // SDIM*SDIM
#define TOT (NB*SS)

#define T_FOV 0.08748866352592401f   // tan(10/360*pi)
#define EPSV 1e-7f
#define ONE_M_EPS 0.99999990f        // float(1.0 - 1e-7)
#define INV_GAMMA 0.45454545454545453f
#define GAMMA_F 2.2f

// Scratch (no allocations allowed)
static __device__ float g_params[NB * 8];   // la, lb, spec_alpha, spec_strength, ldx, ldy, ldz
static __device__ float g_min_depth[NB];
static __device__ float g_shadow[TOT];

// Normalized 1D Gaussian weights (ksize=7, sigma=2); separable form of the
// reference's outer(g,g)/sum 2D kernel.
__constant__ float GW[7] = {0.07015933f, 0.13107488f, 0.19071282f,
                            0.21610594f,
                            0.19071282f, 0.13107488f, 0.07015933f};

__global__ void params_kernel(const float* __restrict__ netL,
                              const float* __restrict__ light) {
    int b = threadIdx.x;
    if (b >= NB) return;
    float t0 = tanhf(netL[b * 6 + 0]);
    float t1 = tanhf(netL[b * 6 + 1]);
    float t2 = tanhf(netL[b * 6 + 2]);
    float t5 = tanhf(netL[b * 6 + 5]);
    const float t_alpha = 10.313708498984761f;   // sqrt(128) - 1
    float sa = (t0 * 0.5f + 0.5f) * t_alpha + 1.0f;
    float* p = g_params + b * 8;
    p[0] = t1 * 0.5f + 0.5f;                  // light_a
    p[1] = t2 * 0.5f + 0.5f;                  // light_b
    p[2] = sa * sa;                           // spec_alpha
    p[3] = (t5 * 0.5f + 0.5f) * 0.5f;         // spec_strength
    float lx = light[b * 2 + 0];
    float ly = light[b * 2 + 1];
    float n = sqrtf(lx * lx + ly * ly + 1.0f);
    p[4] = lx / n;
    p[5] = ly / n;
    p[6] = 1.0f / n;
}

__global__ void mindepth_kernel(const float* __restrict__ depth) {
    __shared__ float red[256];
    int b = blockIdx.x;
    const float* d = depth + b * SS;
    float m = 1e30f;
    for (int i = threadIdx.x; i < SS; i += 256) m = fminf(m, d[i]);
    red[threadIdx.x] = m;
    __syncthreads();
    for (int s = 128; s > 0; s >>= 1) {
        if (threadIdx.x < s) red[threadIdx.x] = fminf(red[threadIdx.x], red[threadIdx.x + s]);
        __syncthreads();
    }
    if (threadIdx.x == 0) g_min_depth[b] = red[0];
}

__global__ void __launch_bounds__(256) shadow_kernel(const float* __restrict__ depth) {
    int idx = blockIdx.x * blockDim.x + threadIdx.x;
    if (idx >= TOT) return;
    int b = idx >> 16;
    int p = idx & (SS - 1);
    int i = p >> 8;
    int j = p & 255;

    const float* dimg = depth + b * SS;
    float d = __ldg(dimg + p);

    // c[k] = (-1 + k*(2/255)) * t  (matches jnp.linspace(-1,1,256)*t)
    float ci = __fmul_rn(__fadd_rn(__fmul_rn((float)i, 2.0f / 255.0f), -1.0f), T_FOV);
    float cj = __fmul_rn(__fadd_rn(__fmul_rn((float)j, 2.0f / 255.0f), -1.0f), T_FOV);

    float px0 = cj * d, py0 = ci * d;
    const float* prm = g_params + b * 8;
    float sx = -prm[4] * (1.0f / 256.0f);
    float sy = -prm[5] * (1.0f / 256.0f);
    float sz = -prm[6] * (1.0f / 256.0f);       // strictly negative
    float minz = g_min_depth[b] - 1e-5f;        // margin vs bilinear/fp rounding

    // Steps with pz >= minz: pz_k = d + k*sz. Any bilinear sample is a convex
    // combination of depths >= min_depth, so shadow is impossible once pz<minz.
    float nf = fminf(floorf((d - minz) * __fdividef(-1.0f, sz)), 256.0f);
    int n = (int)nf;

    const float W = 128.0f / T_FOV;
    float sh = 0.0f;
    for (int k = 1; k <= n && sh == 0.0f; k += 4) {
        #pragma unroll
        for (int u = 0; u < 4; u++) {
            // clamp trailing lanes to step n (duplicate of a valid step -> safe)
            float kk = fminf((float)(k + u), nf);
            float pzz = fmaf(kk, sz, d);
            float rz = __fdividef(1.0f, pzz);
            float x = fmaf(fmaf(kk, sx, px0) * W, rz, 127.5f);
            float y = fmaf(fmaf(kk, sy, py0) * W, rz, 127.5f);
            float x0f = floorf(x);
            float y0f = floorf(y);
            float wx = x - x0f;
            float wy = y - y0f;
            int x0 = (int)x0f;
            int y0 = (int)y0f;
            int x0i = min(max(x0, 0), 255);
            int x1i = min(max(x0 + 1, 0), 255);
            int y0i = min(max(y0, 0), 255);
            int y1i = min(max(y0 + 1, 0), 255);
            float v00 = __ldg(dimg + y0i * SDIM + x0i);
            float v01 = __ldg(dimg + y0i * SDIM + x1i);
            float v10 = __ldg(dimg + y1i * SDIM + x0i);
            float v11 = __ldg(dimg + y1i * SDIM + x1i);
            float sampled = v00 * (1.0f - wx) * (1.0f - wy)
                          + v01 * wx * (1.0f - wy)
                          + v10 * (1.0f - wx) * wy
                          + v11 * wx * wy;
            if (sampled < pzz) sh = 1.0f;
        }
    }
    g_shadow[idx] = sh;
}

// Fused: 7x7 separable Gaussian blur of shadow (smem tile) + Phong epilogue.
// Block = 32x32 output tile; apron = 3.
__global__ void __launch_bounds__(1024) final_kernel(const float* __restrict__ netA,
                                                     const float* __restrict__ normal,
                                                     float* __restrict__ out) {
    __shared__ float s_sh[38][40];
    __shared__ float s_hb[38][33];

    int b = blockIdx.z;
    int ti0 = blockIdx.y * 32;
    int tj0 = blockIdx.x * 32;
    int tx = threadIdx.x;
    int ty = threadIdx.y;
    int tid = ty * 32 + tx;

    const float* shb = g_shadow + b * SS;

    // Load 38x38 shadow tile with zero padding
    for (int t = tid; t < 38 * 38; t += 1024) {
        int r = t / 38;
        int c = t - r * 38;
        int gi = ti0 - 3 + r;
        int gj = tj0 - 3 + c;
        float v = 0.0f;
        if (gi >= 0 && gi < SDIM && gj >= 0 && gj < SDIM) v = shb[gi * SDIM + gj];
        s_sh[r][c] = v;
    }
    __syncthreads();

    // Horizontal blur: 38 rows x 32 cols
    for (int t = tid; t < 38 * 32; t += 1024) {
        int r = t >> 5;
        int c = t & 31;
        float acc = 0.0f;
        #pragma unroll
        for (int dj = 0; dj < 7; dj++) acc += GW[dj] * s_sh[r][c + dj];
        s_hb[r][c] = acc;
    }
    __syncthreads();

    // Vertical blur for this thread's pixel
    float ssum = 0.0f;
    #pragma unroll
    for (int dy = 0; dy < 7; dy++) ssum += GW[dy] * s_hb[ty + dy][tx];
    float shadow_factor = fminf(fmaxf(1.0f - ssum, 0.1f), 1.0f);

    int i = ti0 + ty;
    int j = tj0 + tx;
    int p = i * SDIM + j;

    const float* prm = g_params + b * 8;
    float la = prm[0], lb = prm[1], spec_alpha = prm[2], spec_strength = prm[3];
    float ldx = prm[4], ldy = prm[5], ldz = prm[6];

    const float* nb = normal + b * 3 * SS;
    float nx = __ldg(nb + p);
    float ny = __ldg(nb + SS + p);
    float nz = __ldg(nb + 2 * SS + p);

    float cosb = nx * ldx + ny * ldy + nz * ldz;
    float diffuse = fmaxf(cosb, 0.0f);

    // view_d = normalize(-x[j], -x[i], 1) via flipped linspace indexing
    float aj = __fmul_rn(__fadd_rn(__fmul_rn((float)(255 - j), 2.0f / 255.0f), -1.0f), T_FOV);
    float ai = __fmul_rn(__fadd_rn(__fmul_rn((float)(255 - i), 2.0f / 255.0f), -1.0f), T_FOV);
    float rnrm = rsqrtf(ai * ai + aj * aj + 1.0f);
    float vdx = aj * rnrm, vdy = ai * rnrm, vdz = rnrm;

    float rdx = 2.0f * cosb * nx - ldx;
    float rdy = 2.0f * cosb * ny - ldy;
    float rdz = 2.0f * cosb * nz - ldz;

    float mask = (i >= 5 && i < SDIM - 5 && j >= 5 && j < SDIM - 5) ? 1.0f : 0.0f;
    float spec = fmaxf(vdx * rdx + vdy * rdy + vdz * rdz, 0.0f)
               * ((cosb > 0.0f) ? 1.0f : 0.0f) * mask;
    float specc = fminf(fmaxf(spec, EPSV), ONE_M_EPS);
    float spec_sh = __powf(specc, spec_alpha);

    float shading = la + lb * diffuse * shadow_factor;
    float term2 = spec_strength * lb * spec_sh;

    // albedo^GAMMA where albedo = tanh(a)/2 + 0.5 = sigmoid(2a):
    //   sigmoid(2a)^G = exp2(-G * log2(1 + exp2(-2a*log2(e))))
    const float NLOG2E2 = -2.8853900817779268f;   // -2*log2(e)
    const float* ab = netA + b * 5 * SS;
    float* ob = out + b * 3 * SS;
    #pragma unroll
    for (int c = 0; c < 3; c++) {
        float a = __ldg(ab + c * SS + p);
        float u = exp2f(a * NLOG2E2);
        float alb = exp2f(-GAMMA_F * __log2f(1.0f + u));
        float r = alb * shading + term2;
        ob[c * SS + p] = __powf(fmaxf(r, EPSV), INV_GAMMA);
    }
}

extern "C" void kernel_launch(void* const* d_in, const int* in_sizes, int n_in,
                              void* d_out, int out_size) {
    const float* netA   = (const float*)d_in[0];
    const float* netL   = (const float*)d_in[1];
    const float* normal = (const float*)d_in[2];
    const float* depth  = (const float*)d_in[3];
    const float* light  = (const float*)d_in[4];
    float* out = (float*)d_out;

    params_kernel<<<1, 32>>>(netL, light);
    mindepth_kernel<<<NB, 256>>>(depth);
    shadow_kernel<<<TOT / 256, 256>>>(depth);
    dim3 grid(SDIM / 32, SDIM / 32, NB);
    dim3 blk(32, 32);
    final_kernel<<<grid, blk>>>(netA, normal, out);
}

// round 6
// speedup vs baseline: 1.6774x; 1.2454x over previous
#include <cuda_runtime.h>
#include <math.h>

#define NB 32
#define SDIM 256
#define SS 65536            // SDIM*SDIM
#define TOT (NB*SS)

#define T_FOV 0.08748866352592401f   // tan(10/360*pi)
#define EPSV 1e-7f
#define ONE_M_EPS 0.99999990f        // float(1.0 - 1e-7)
#define INV_GAMMA 0.45454545454545453f
#define GAMMA_F 2.2f

// Scratch (no allocations allowed)
static __device__ float g_params[NB * 8];   // la, lb, spec_alpha, spec_strength, ldx, ldy, ldz
static __device__ int   g_min_bits[NB];     // min depth as positive-float bits
static __device__ float g_shadow[TOT];
static __device__ float4 g_quad[TOT];       // (v00, v01, v10, v11) border-clamped, 32MB

// Normalized 1D Gaussian weights (ksize=7, sigma=2); separable form of the
// reference's outer(g,g)/sum 2D kernel.
__constant__ float GW[7] = {0.07015933f, 0.13107488f, 0.19071282f,
                            0.21610594f,
                            0.19071282f, 0.13107488f, 0.07015933f};

__global__ void params_kernel(const float* __restrict__ netL,
                              const float* __restrict__ light) {
    int b = threadIdx.x;
    if (b >= NB) return;
    float t0 = tanhf(netL[b * 6 + 0]);
    float t1 = tanhf(netL[b * 6 + 1]);
    float t2 = tanhf(netL[b * 6 + 2]);
    float t5 = tanhf(netL[b * 6 + 5]);
    const float t_alpha = 10.313708498984761f;   // sqrt(128) - 1
    float sa = (t0 * 0.5f + 0.5f) * t_alpha + 1.0f;
    float* p = g_params + b * 8;
    p[0] = t1 * 0.5f + 0.5f;                  // light_a
    p[1] = t2 * 0.5f + 0.5f;                  // light_b
    p[2] = sa * sa;                           // spec_alpha
    p[3] = (t5 * 0.5f + 0.5f) * 0.5f;         // spec_strength
    float lx = light[b * 2 + 0];
    float ly = light[b * 2 + 1];
    float n = sqrtf(lx * lx + ly * ly + 1.0f);
    p[4] = lx / n;
    p[5] = ly / n;
    p[6] = 1.0f / n;
    g_min_bits[b] = 0x7f7fffff;               // +FLT_MAX bits
}

// Build bilinear quad image + per-batch min-depth (positive-float atomicMin).
// One block = one image row (256 threads), so the block has a single batch.
__global__ void __launch_bounds__(256) quad_kernel(const float* __restrict__ depth) {
    int idx = blockIdx.x * 256 + threadIdx.x;
    int b = idx >> 16;
    int p = idx & (SS - 1);
    int y = p >> 8;
    int x = p & 255;
    const float* dimg = depth + b * SS;
    int x1 = min(x + 1, 255);
    int y1 = min(y + 1, 255);
    float4 q;
    q.x = __ldg(dimg + y  * SDIM + x);
    q.y = __ldg(dimg + y  * SDIM + x1);
    q.z = __ldg(dimg + y1 * SDIM + x);
    q.w = __ldg(dimg + y1 * SDIM + x1);
    g_quad[idx] = q;

    // block-min of own depth (q.x), then one atomic per block
    float m = q.x;
    #pragma unroll
    for (int s = 16; s > 0; s >>= 1)
        m = fminf(m, __shfl_xor_sync(0xffffffffu, m, s));
    __shared__ float warp_min[8];
    if ((threadIdx.x & 31) == 0) warp_min[threadIdx.x >> 5] = m;
    __syncthreads();
    if (threadIdx.x == 0) {
        float bm = warp_min[0];
        #pragma unroll
        for (int w = 1; w < 8; w++) bm = fminf(bm, warp_min[w]);
        atomicMin(&g_min_bits[b], __float_as_int(bm));   // valid: all positive
    }
}

__global__ void __launch_bounds__(256) shadow_kernel(const float* __restrict__ depth) {
    int idx = blockIdx.x * blockDim.x + threadIdx.x;
    int b = idx >> 16;
    int p = idx & (SS - 1);
    int i = p >> 8;
    int j = p & 255;

    float d = __ldg(depth + b * SS + p);
    const float4* quad = g_quad + b * SS;

    // c[k] = (-1 + k*(2/255)) * t  (matches jnp.linspace(-1,1,256)*t)
    float ci = __fmul_rn(__fadd_rn(__fmul_rn((float)i, 2.0f / 255.0f), -1.0f), T_FOV);
    float cj = __fmul_rn(__fadd_rn(__fmul_rn((float)j, 2.0f / 255.0f), -1.0f), T_FOV);

    float px0 = cj * d, py0 = ci * d;
    const float* prm = g_params + b * 8;
    float sx = -prm[4] * (1.0f / 256.0f);
    float sy = -prm[5] * (1.0f / 256.0f);
    float sz = -prm[6] * (1.0f / 256.0f);       // strictly negative
    float minz = __int_as_float(g_min_bits[b]) - 1e-5f;

    // Steps with pz >= minz: pz_k = d + k*sz. Any bilinear sample is a convex
    // combination of depths >= min_depth, so shadow is impossible once pz<minz.
    float nf = fminf(floorf((d - minz) * __fdividef(-1.0f, sz)), 256.0f);
    int n = (int)nf;

    const float W = 128.0f / T_FOV;
    float sh = 0.0f;
    for (int k = 1; k <= n && sh == 0.0f; k += 8) {
        #pragma unroll
        for (int u = 0; u < 8; u++) {
            // clamp trailing lanes to step n (duplicate of a valid step -> safe)
            float kk = fminf((float)(k + u), nf);
            float pzz = fmaf(kk, sz, d);
            float rz = __fdividef(1.0f, pzz);
            float x = fmaf(fmaf(kk, sx, px0) * W, rz, 127.5f);
            float y = fmaf(fmaf(kk, sy, py0) * W, rz, 127.5f);
            // Clamp continuous coords: outside [0,255] the border-sampled value
            // equals the edge value, which the clamped coord + quad reproduces
            // (wx -> 0 exactly where indices would have collapsed).
            x = fminf(fmaxf(x, 0.0f), 255.0f);
            y = fminf(fmaxf(y, 0.0f), 255.0f);
            float x0f = floorf(x);
            float y0f = floorf(y);
            float wx = x - x0f;
            float wy = y - y0f;
            int x0i = (int)x0f;
            int y0i = (int)y0f;
            float4 q = __ldg(quad + y0i * SDIM + x0i);
            float sampled = q.x * (1.0f - wx) * (1.0f - wy)
                          + q.y * wx * (1.0f - wy)
                          + q.z * (1.0f - wx) * wy
                          + q.w * wx * wy;
            if (sampled < pzz) sh = 1.0f;
        }
    }
    g_shadow[idx] = sh;
}

// Fused: 7x7 separable Gaussian blur of shadow (smem tile) + Phong epilogue.
// Block = 32x32 output tile; apron = 3.
__global__ void __launch_bounds__(1024) final_kernel(const float* __restrict__ netA,
                                                     const float* __restrict__ normal,
                                                     float* __restrict__ out) {
    __shared__ float s_sh[38][40];
    __shared__ float s_hb[38][33];

    int b = blockIdx.z;
    int ti0 = blockIdx.y * 32;
    int tj0 = blockIdx.x * 32;
    int tx = threadIdx.x;
    int ty = threadIdx.y;
    int tid = ty * 32 + tx;

    const float* shb = g_shadow + b * SS;

    // Load 38x38 shadow tile with zero padding
    for (int t = tid; t < 38 * 38; t += 1024) {
        int r = t / 38;
        int c = t - r * 38;
        int gi = ti0 - 3 + r;
        int gj = tj0 - 3 + c;
        float v = 0.0f;
        if (gi >= 0 && gi < SDIM && gj >= 0 && gj < SDIM) v = shb[gi * SDIM + gj];
        s_sh[r][c] = v;
    }
    __syncthreads();

    // Horizontal blur: 38 rows x 32 cols
    for (int t = tid; t < 38 * 32; t += 1024) {
        int r = t >> 5;
        int c = t & 31;
        float acc = 0.0f;
        #pragma unroll
        for (int dj = 0; dj < 7; dj++) acc += GW[dj] * s_sh[r][c + dj];
        s_hb[r][c] = acc;
    }
    __syncthreads();

    // Vertical blur for this thread's pixel
    float ssum = 0.0f;
    #pragma unroll
    for (int dy = 0; dy < 7; dy++) ssum += GW[dy] * s_hb[ty + dy][tx];
    float shadow_factor = fminf(fmaxf(1.0f - ssum, 0.1f), 1.0f);

    int i = ti0 + ty;
    int j = tj0 + tx;
    int p = i * SDIM + j;

    const float* prm = g_params + b * 8;
    float la = prm[0], lb = prm[1], spec_alpha = prm[2], spec_strength = prm[3];
    float ldx = prm[4], ldy = prm[5], ldz = prm[6];

    const float* nb = normal + b * 3 * SS;
    float nx = __ldg(nb + p);
    float ny = __ldg(nb + SS + p);
    float nz = __ldg(nb + 2 * SS + p);

    float cosb = nx * ldx + ny * ldy + nz * ldz;
    float diffuse = fmaxf(cosb, 0.0f);

    // view_d = normalize(-x[j], -x[i], 1) via flipped linspace indexing
    float aj = __fmul_rn(__fadd_rn(__fmul_rn((float)(255 - j), 2.0f / 255.0f), -1.0f), T_FOV);
    float ai = __fmul_rn(__fadd_rn(__fmul_rn((float)(255 - i), 2.0f / 255.0f), -1.0f), T_FOV);
    float rnrm = rsqrtf(ai * ai + aj * aj + 1.0f);
    float vdx = aj * rnrm, vdy = ai * rnrm, vdz = rnrm;

    float rdx = 2.0f * cosb * nx - ldx;
    float rdy = 2.0f * cosb * ny - ldy;
    float rdz = 2.0f * cosb * nz - ldz;

    float mask = (i >= 5 && i < SDIM - 5 && j >= 5 && j < SDIM - 5) ? 1.0f : 0.0f;
    float spec = fmaxf(vdx * rdx + vdy * rdy + vdz * rdz, 0.0f)
               * ((cosb > 0.0f) ? 1.0f : 0.0f) * mask;
    float specc = fminf(fmaxf(spec, EPSV), ONE_M_EPS);
    float spec_sh = __powf(specc, spec_alpha);

    float shading = la + lb * diffuse * shadow_factor;
    float term2 = spec_strength * lb * spec_sh;

    // albedo^GAMMA where albedo = tanh(a)/2 + 0.5 = sigmoid(2a):
    //   sigmoid(2a)^G = exp2(-G * log2(1 + exp2(-2a*log2(e))))
    const float NLOG2E2 = -2.8853900817779268f;   // -2*log2(e)
    const float* ab = netA + b * 5 * SS;
    float* ob = out + b * 3 * SS;
    #pragma unroll
    for (int c = 0; c < 3; c++) {
        float a = __ldg(ab + c * SS + p);
        float u = exp2f(a * NLOG2E2);
        float alb = exp2f(-GAMMA_F * __log2f(1.0f + u));
        float r = alb * shading + term2;
        ob[c * SS + p] = __powf(fmaxf(r, EPSV), INV_GAMMA);
    }
}

extern "C" void kernel_launch(void* const* d_in, const int* in_sizes, int n_in,
                              void* d_out, int out_size) {
    const float* netA   = (const float*)d_in[0];
    const float* netL   = (const float*)d_in[1];
    const float* normal = (const float*)d_in[2];
    const float* depth  = (const float*)d_in[3];
    const float* light  = (const float*)d_in[4];
    float* out = (float*)d_out;

    params_kernel<<<1, 32>>>(netL, light);
    quad_kernel<<<TOT / 256, 256>>>(depth);
    shadow_kernel<<<TOT / 256, 256>>>(depth);
    dim3 grid(SDIM / 32, SDIM / 32, NB);
    dim3 blk(32, 32);
    final_kernel<<<grid, blk>>>(netA, normal, out);
}

// round 7
// speedup vs baseline: 2.1936x; 1.3078x over previous
#include <cuda_runtime.h>
#include <math.h>

#define NB 32
#define SDIM 256
#define SS 65536            // SDIM*SDIM
#define TOT (NB*SS)

#define T_FOV 0.08748866352592401f   // tan(10/360*pi)
#define EPSV 1e-7f
#define ONE_M_EPS 0.99999990f        // float(1.0 - 1e-7)
#define INV_GAMMA 0.45454545454545453f
#define GAMMA_F 2.2f
#define P1_STEPS 16                  // phase-1 step cap (2 chunks of 8)

// Scratch (no allocations allowed)
static __device__ float g_params[NB * 8];   // la, lb, spec_alpha, spec_strength, ldx, ldy, ldz
static __device__ int   g_min_bits[NB];     // min depth as positive-float bits
static __device__ float g_shadow[TOT];
static __device__ float4 g_quad[TOT];       // (v00, v01, v10, v11) border-clamped, 32MB
static __device__ int   g_queue[TOT];       // survivor ray indices
static __device__ int   g_qcount;

// Normalized 1D Gaussian weights (ksize=7, sigma=2); separable form of the
// reference's outer(g,g)/sum 2D kernel.
__constant__ float GW[7] = {0.07015933f, 0.13107488f, 0.19071282f,
                            0.21610594f,
                            0.19071282f, 0.13107488f, 0.07015933f};

__global__ void params_kernel(const float* __restrict__ netL,
                              const float* __restrict__ light) {
    int b = threadIdx.x;
    if (b == 0) g_qcount = 0;
    if (b >= NB) return;
    float t0 = tanhf(netL[b * 6 + 0]);
    float t1 = tanhf(netL[b * 6 + 1]);
    float t2 = tanhf(netL[b * 6 + 2]);
    float t5 = tanhf(netL[b * 6 + 5]);
    const float t_alpha = 10.313708498984761f;   // sqrt(128) - 1
    float sa = (t0 * 0.5f + 0.5f) * t_alpha + 1.0f;
    float* p = g_params + b * 8;
    p[0] = t1 * 0.5f + 0.5f;                  // light_a
    p[1] = t2 * 0.5f + 0.5f;                  // light_b
    p[2] = sa * sa;                           // spec_alpha
    p[3] = (t5 * 0.5f + 0.5f) * 0.5f;         // spec_strength
    float lx = light[b * 2 + 0];
    float ly = light[b * 2 + 1];
    float n = sqrtf(lx * lx + ly * ly + 1.0f);
    p[4] = lx / n;
    p[5] = ly / n;
    p[6] = 1.0f / n;
    g_min_bits[b] = 0x7f7fffff;               // +FLT_MAX bits
}

// Build bilinear quad image + per-batch min-depth (positive-float atomicMin).
__global__ void __launch_bounds__(256) quad_kernel(const float* __restrict__ depth) {
    int idx = blockIdx.x * 256 + threadIdx.x;
    int b = idx >> 16;
    int p = idx & (SS - 1);
    int y = p >> 8;
    int x = p & 255;
    const float* dimg = depth + b * SS;
    int x1 = min(x + 1, 255);
    int y1 = min(y + 1, 255);
    float4 q;
    q.x = __ldg(dimg + y  * SDIM + x);
    q.y = __ldg(dimg + y  * SDIM + x1);
    q.z = __ldg(dimg + y1 * SDIM + x);
    q.w = __ldg(dimg + y1 * SDIM + x1);
    g_quad[idx] = q;

    float m = q.x;
    #pragma unroll
    for (int s = 16; s > 0; s >>= 1)
        m = fminf(m, __shfl_xor_sync(0xffffffffu, m, s));
    __shared__ float warp_min[8];
    if ((threadIdx.x & 31) == 0) warp_min[threadIdx.x >> 5] = m;
    __syncthreads();
    if (threadIdx.x == 0) {
        float bm = warp_min[0];
        #pragma unroll
        for (int w = 1; w < 8; w++) bm = fminf(bm, warp_min[w]);
        atomicMin(&g_min_bits[b], __float_as_int(bm));   // valid: all positive
    }
}

// One raymarch step k (closed-form position). Returns sampled < pz.
__device__ __forceinline__ bool march_step(float kk, float d, float sz,
                                           float sx, float sy,
                                           float px0, float py0,
                                           const float4* __restrict__ quad) {
    const float W = 128.0f / T_FOV;
    float pzz = fmaf(kk, sz, d);
    float rz = __fdividef(1.0f, pzz);
    float x = fmaf(fmaf(kk, sx, px0) * W, rz, 127.5f);
    float y = fmaf(fmaf(kk, sy, py0) * W, rz, 127.5f);
    x = fminf(fmaxf(x, 0.0f), 255.0f);
    y = fminf(fmaxf(y, 0.0f), 255.0f);
    float x0f = floorf(x);
    float y0f = floorf(y);
    float wx = x - x0f;
    float wy = y - y0f;
    int x0i = (int)x0f;
    int y0i = (int)y0f;
    float4 q = __ldg(quad + y0i * SDIM + x0i);
    float sampled = q.x * (1.0f - wx) * (1.0f - wy)
                  + q.y * wx * (1.0f - wy)
                  + q.z * (1.0f - wx) * wy
                  + q.w * wx * wy;
    return sampled < pzz;
}

// Phase 1: bounded march (<= P1_STEPS). Survivors pushed to queue.
__global__ void __launch_bounds__(256) shadow1_kernel(const float* __restrict__ depth) {
    int idx = blockIdx.x * blockDim.x + threadIdx.x;
    int b = idx >> 16;
    int p = idx & (SS - 1);
    int i = p >> 8;
    int j = p & 255;

    float d = __ldg(depth + b * SS + p);
    const float4* quad = g_quad + b * SS;

    float ci = __fmul_rn(__fadd_rn(__fmul_rn((float)i, 2.0f / 255.0f), -1.0f), T_FOV);
    float cj = __fmul_rn(__fadd_rn(__fmul_rn((float)j, 2.0f / 255.0f), -1.0f), T_FOV);

    float px0 = cj * d, py0 = ci * d;
    const float* prm = g_params + b * 8;
    float sx = -prm[4] * (1.0f / 256.0f);
    float sy = -prm[5] * (1.0f / 256.0f);
    float sz = -prm[6] * (1.0f / 256.0f);       // strictly negative
    float minz = __int_as_float(g_min_bits[b]) - 1e-5f;

    float nf = fminf(floorf((d - minz) * __fdividef(-1.0f, sz)), 256.0f);
    int n = (int)nf;

    int ncap = min(n, P1_STEPS);
    float sh = 0.0f;
    for (int k = 1; k <= ncap && sh == 0.0f; k += 8) {
        #pragma unroll
        for (int u = 0; u < 8; u++) {
            float kk = fminf((float)(k + u), nf);
            if (march_step(kk, d, sz, sx, sy, px0, py0, quad)) sh = 1.0f;
        }
    }
    g_shadow[idx] = sh;

    // Warp-aggregated survivor push
    bool surv = (sh == 0.0f) && (n > P1_STEPS);
    unsigned mask = __ballot_sync(0xffffffffu, surv);
    if (mask) {
        int lane = threadIdx.x & 31;
        int leader = __ffs(mask) - 1;
        int base = 0;
        if (lane == leader) base = atomicAdd(&g_qcount, __popc(mask));
        base = __shfl_sync(0xffffffffu, base, leader);
        if (surv) g_queue[base + __popc(mask & ((1u << lane) - 1u))] = idx;
    }
}

// Phase 2: dense march of survivors from k = P1_STEPS+1.
__global__ void __launch_bounds__(256) shadow2_kernel(const float* __restrict__ depth) {
    int total = g_qcount;
    for (int q = blockIdx.x * blockDim.x + threadIdx.x; q < total;
         q += gridDim.x * blockDim.x) {
        int idx = g_queue[q];
        int b = idx >> 16;
        int p = idx & (SS - 1);
        int i = p >> 8;
        int j = p & 255;

        float d = __ldg(depth + b * SS + p);
        const float4* quad = g_quad + b * SS;

        float ci = __fmul_rn(__fadd_rn(__fmul_rn((float)i, 2.0f / 255.0f), -1.0f), T_FOV);
        float cj = __fmul_rn(__fadd_rn(__fmul_rn((float)j, 2.0f / 255.0f), -1.0f), T_FOV);

        float px0 = cj * d, py0 = ci * d;
        const float* prm = g_params + b * 8;
        float sx = -prm[4] * (1.0f / 256.0f);
        float sy = -prm[5] * (1.0f / 256.0f);
        float sz = -prm[6] * (1.0f / 256.0f);
        float minz = __int_as_float(g_min_bits[b]) - 1e-5f;

        float nf = fminf(floorf((d - minz) * __fdividef(-1.0f, sz)), 256.0f);
        int n = (int)nf;

        float sh = 0.0f;
        for (int k = P1_STEPS + 1; k <= n && sh == 0.0f; k += 8) {
            #pragma unroll
            for (int u = 0; u < 8; u++) {
                float kk = fminf((float)(k + u), nf);
                if (march_step(kk, d, sz, sx, sy, px0, py0, quad)) sh = 1.0f;
            }
        }
        if (sh != 0.0f) g_shadow[idx] = 1.0f;
    }
}

// Fused: 7x7 separable Gaussian blur of shadow (smem tile) + Phong epilogue.
__global__ void __launch_bounds__(1024) final_kernel(const float* __restrict__ netA,
                                                     const float* __restrict__ normal,
                                                     float* __restrict__ out) {
    __shared__ float s_sh[38][40];
    __shared__ float s_hb[38][33];

    int b = blockIdx.z;
    int ti0 = blockIdx.y * 32;
    int tj0 = blockIdx.x * 32;
    int tx = threadIdx.x;
    int ty = threadIdx.y;
    int tid = ty * 32 + tx;

    const float* shb = g_shadow + b * SS;

    for (int t = tid; t < 38 * 38; t += 1024) {
        int r = t / 38;
        int c = t - r * 38;
        int gi = ti0 - 3 + r;
        int gj = tj0 - 3 + c;
        float v = 0.0f;
        if (gi >= 0 && gi < SDIM && gj >= 0 && gj < SDIM) v = shb[gi * SDIM + gj];
        s_sh[r][c] = v;
    }
    __syncthreads();

    for (int t = tid; t < 38 * 32; t += 1024) {
        int r = t >> 5;
        int c = t & 31;
        float acc = 0.0f;
        #pragma unroll
        for (int dj = 0; dj < 7; dj++) acc += GW[dj] * s_sh[r][c + dj];
        s_hb[r][c] = acc;
    }
    __syncthreads();

    float ssum = 0.0f;
    #pragma unroll
    for (int dy = 0; dy < 7; dy++) ssum += GW[dy] * s_hb[ty + dy][tx];
    float shadow_factor = fminf(fmaxf(1.0f - ssum, 0.1f), 1.0f);

    int i = ti0 + ty;
    int j = tj0 + tx;
    int p = i * SDIM + j;

    const float* prm = g_params + b * 8;
    float la = prm[0], lb = prm[1], spec_alpha = prm[2], spec_strength = prm[3];
    float ldx = prm[4], ldy = prm[5], ldz = prm[6];

    const float* nb = normal + b * 3 * SS;
    float nx = __ldg(nb + p);
    float ny = __ldg(nb + SS + p);
    float nz = __ldg(nb + 2 * SS + p);

    float cosb = nx * ldx + ny * ldy + nz * ldz;
    float diffuse = fmaxf(cosb, 0.0f);

    float aj = __fmul_rn(__fadd_rn(__fmul_rn((float)(255 - j), 2.0f / 255.0f), -1.0f), T_FOV);
    float ai = __fmul_rn(__fadd_rn(__fmul_rn((float)(255 - i), 2.0f / 255.0f), -1.0f), T_FOV);
    float rnrm = rsqrtf(ai * ai + aj * aj + 1.0f);
    float vdx = aj * rnrm, vdy = ai * rnrm, vdz = rnrm;

    float rdx = 2.0f * cosb * nx - ldx;
    float rdy = 2.0f * cosb * ny - ldy;
    float rdz = 2.0f * cosb * nz - ldz;

    float mask = (i >= 5 && i < SDIM - 5 && j >= 5 && j < SDIM - 5) ? 1.0f : 0.0f;
    float spec = fmaxf(vdx * rdx + vdy * rdy + vdz * rdz, 0.0f)
               * ((cosb > 0.0f) ? 1.0f : 0.0f) * mask;
    float specc = fminf(fmaxf(spec, EPSV), ONE_M_EPS);
    float spec_sh = __powf(specc, spec_alpha);

    float shading = la + lb * diffuse * shadow_factor;
    float term2 = spec_strength * lb * spec_sh;

    const float NLOG2E2 = -2.8853900817779268f;   // -2*log2(e)
    const float* ab = netA + b * 5 * SS;
    float* ob = out + b * 3 * SS;
    #pragma unroll
    for (int c = 0; c < 3; c++) {
        float a = __ldg(ab + c * SS + p);
        float u = exp2f(a * NLOG2E2);
        float alb = exp2f(-GAMMA_F * __log2f(1.0f + u));
        float r = alb * shading + term2;
        ob[c * SS + p] = __powf(fmaxf(r, EPSV), INV_GAMMA);
    }
}

extern "C" void kernel_launch(void* const* d_in, const int* in_sizes, int n_in,
                              void* d_out, int out_size) {
    const float* netA   = (const float*)d_in[0];
    const float* netL   = (const float*)d_in[1];
    const float* normal = (const float*)d_in[2];
    const float* depth  = (const float*)d_in[3];
    const float* light  = (const float*)d_in[4];
    float* out = (float*)d_out;

    params_kernel<<<1, 32>>>(netL, light);
    quad_kernel<<<TOT / 256, 256>>>(depth);
    shadow1_kernel<<<TOT / 256, 256>>>(depth);
    shadow2_kernel<<<1184, 256>>>(depth);   // 8 blocks/SM * 148 SMs
    dim3 grid(SDIM / 32, SDIM / 32, NB);
    dim3 blk(32, 32);
    final_kernel<<<grid, blk>>>(netA, normal, out);
}

// round 8
// speedup vs baseline: 2.2034x; 1.0045x over previous
#include <cuda_runtime.h>
#include <math.h>

#define NB 32
#define SDIM 256
#define SS 65536            // SDIM*SDIM
#define TOT (NB*SS)

#define T_FOV 0.08748866352592401f   // tan(10/360*pi)
#define EPSV 1e-7f
#define ONE_M_EPS 0.99999990f        // float(1.0 - 1e-7)
#define INV_GAMMA 0.45454545454545453f
#define GAMMA_F 2.2f
#define P1_STEPS 16                  // phase-1 step cap (2 chunks of 8)

// Scratch (no allocations allowed)
static __device__ float g_params[NB * 8];   // la, lb, spec_alpha, spec_strength, ldx, ldy, ldz, eps^alpha
static __device__ int   g_min_bits[NB];     // min depth as positive-float bits
static __device__ float g_shadow[TOT];
static __device__ float4 g_quad[TOT];       // (v00, v01, v10, v11) border-clamped, 32MB
static __device__ int   g_queue[TOT];       // survivor ray indices
static __device__ int   g_qcount;

// Normalized 1D Gaussian weights (ksize=7, sigma=2); separable form of the
// reference's outer(g,g)/sum 2D kernel.
__constant__ float GW[7] = {0.07015933f, 0.13107488f, 0.19071282f,
                            0.21610594f,
                            0.19071282f, 0.13107488f, 0.07015933f};

__global__ void params_kernel(const float* __restrict__ netL,
                              const float* __restrict__ light) {
    int b = threadIdx.x;
    if (b == 0) g_qcount = 0;
    if (b >= NB) return;
    float t0 = tanhf(netL[b * 6 + 0]);
    float t1 = tanhf(netL[b * 6 + 1]);
    float t2 = tanhf(netL[b * 6 + 2]);
    float t5 = tanhf(netL[b * 6 + 5]);
    const float t_alpha = 10.313708498984761f;   // sqrt(128) - 1
    float sa = (t0 * 0.5f + 0.5f) * t_alpha + 1.0f;
    float spec_alpha = sa * sa;
    float* p = g_params + b * 8;
    p[0] = t1 * 0.5f + 0.5f;                  // light_a
    p[1] = t2 * 0.5f + 0.5f;                  // light_b
    p[2] = spec_alpha;                        // spec_alpha
    p[3] = (t5 * 0.5f + 0.5f) * 0.5f;         // spec_strength
    float lx = light[b * 2 + 0];
    float ly = light[b * 2 + 1];
    float n = sqrtf(lx * lx + ly * ly + 1.0f);
    p[4] = lx / n;
    p[5] = ly / n;
    p[6] = 1.0f / n;
    p[7] = __powf(EPSV, spec_alpha);          // spec_sh when spec clamps to EPS
    g_min_bits[b] = 0x7f7fffff;               // +FLT_MAX bits
}

// Build bilinear quad image + per-batch min-depth (positive-float atomicMin).
__global__ void __launch_bounds__(256) quad_kernel(const float* __restrict__ depth) {
    int idx = blockIdx.x * 256 + threadIdx.x;
    int b = idx >> 16;
    int p = idx & (SS - 1);
    int y = p >> 8;
    int x = p & 255;
    const float* dimg = depth + b * SS;
    int x1 = min(x + 1, 255);
    int y1 = min(y + 1, 255);
    float4 q;
    q.x = __ldg(dimg + y  * SDIM + x);
    q.y = __ldg(dimg + y  * SDIM + x1);
    q.z = __ldg(dimg + y1 * SDIM + x);
    q.w = __ldg(dimg + y1 * SDIM + x1);
    g_quad[idx] = q;

    float m = q.x;
    #pragma unroll
    for (int s = 16; s > 0; s >>= 1)
        m = fminf(m, __shfl_xor_sync(0xffffffffu, m, s));
    __shared__ float warp_min[8];
    if ((threadIdx.x & 31) == 0) warp_min[threadIdx.x >> 5] = m;
    __syncthreads();
    if (threadIdx.x == 0) {
        float bm = warp_min[0];
        #pragma unroll
        for (int w = 1; w < 8; w++) bm = fminf(bm, warp_min[w]);
        atomicMin(&g_min_bits[b], __float_as_int(bm));   // valid: all positive
    }
}

// One chunk of 8 march steps starting at integer step k.
// Single RCP at chunk center m = k+3.5; per-step reciprocal via
// rz = rz_m * (1 - e + e^2 - e^3), e = (kk-m)*(sz*rz_m), |e|<=0.02
// (truncation < 1.5e-7 rel -> ~1e-5 px coordinate error).
__device__ __forceinline__ bool march_chunk8(int k, float nf, float d,
                                             float sx, float sy, float sz,
                                             float px0, float py0,
                                             const float4* __restrict__ quad) {
    const float W = 128.0f / T_FOV;
    float m = (float)k + 3.5f;
    float pzm = fmaf(m, sz, d);
    float rzm = __fdividef(1.0f, pzm);
    float c = sz * rzm;
    bool hit = false;
    #pragma unroll
    for (int u = 0; u < 8; u++) {
        // clamp trailing lanes to step n (duplicate of a valid step -> safe)
        float kk = fminf((float)(k + u), nf);
        float e = (kk - m) * c;
        float t1 = 1.0f - e;
        float t2 = fmaf(-e, t1, 1.0f);
        float pl = fmaf(-e, t2, 1.0f);           // 1 - e + e^2 - e^3
        float rz = rzm * pl;
        float pzz = fmaf(kk, sz, d);
        float x = fmaf(fmaf(kk, sx, px0) * W, rz, 127.5f);
        float y = fmaf(fmaf(kk, sy, py0) * W, rz, 127.5f);
        x = fminf(fmaxf(x, 0.0f), 255.0f);
        y = fminf(fmaxf(y, 0.0f), 255.0f);
        float x0f = floorf(x);
        float y0f = floorf(y);
        float wx = x - x0f;
        float wy = y - y0f;
        int x0i = (int)x0f;
        int y0i = (int)y0f;
        float4 q = __ldg(quad + y0i * SDIM + x0i);
        float sampled = q.x * (1.0f - wx) * (1.0f - wy)
                      + q.y * wx * (1.0f - wy)
                      + q.z * (1.0f - wx) * wy
                      + q.w * wx * wy;
        hit |= (sampled < pzz);
    }
    return hit;
}

// Phase 1: bounded march (<= P1_STEPS). Survivors pushed to queue.
__global__ void __launch_bounds__(256) shadow1_kernel(const float* __restrict__ depth) {
    int idx = blockIdx.x * blockDim.x + threadIdx.x;
    int b = idx >> 16;
    int p = idx & (SS - 1);
    int i = p >> 8;
    int j = p & 255;

    float d = __ldg(depth + b * SS + p);
    const float4* quad = g_quad + b * SS;

    float ci = __fmul_rn(__fadd_rn(__fmul_rn((float)i, 2.0f / 255.0f), -1.0f), T_FOV);
    float cj = __fmul_rn(__fadd_rn(__fmul_rn((float)j, 2.0f / 255.0f), -1.0f), T_FOV);

    float px0 = cj * d, py0 = ci * d;
    const float* prm = g_params + b * 8;
    float sx = -prm[4] * (1.0f / 256.0f);
    float sy = -prm[5] * (1.0f / 256.0f);
    float sz = -prm[6] * (1.0f / 256.0f);       // strictly negative
    float minz = __int_as_float(g_min_bits[b]) - 1e-5f;

    // Steps with pz >= minz: pz_k = d + k*sz. Any bilinear sample is a convex
    // combination of depths >= min_depth, so shadow is impossible once pz<minz.
    float nf = fminf(floorf((d - minz) * __fdividef(-1.0f, sz)), 256.0f);
    int n = (int)nf;

    int ncap = min(n, P1_STEPS);
    float sh = 0.0f;
    for (int k = 1; k <= ncap && sh == 0.0f; k += 8) {
        if (march_chunk8(k, nf, d, sx, sy, sz, px0, py0, quad)) sh = 1.0f;
    }
    g_shadow[idx] = sh;

    // Warp-aggregated survivor push
    bool surv = (sh == 0.0f) && (n > P1_STEPS);
    unsigned mask = __ballot_sync(0xffffffffu, surv);
    if (mask) {
        int lane = threadIdx.x & 31;
        int leader = __ffs(mask) - 1;
        int base = 0;
        if (lane == leader) base = atomicAdd(&g_qcount, __popc(mask));
        base = __shfl_sync(0xffffffffu, base, leader);
        if (surv) g_queue[base + __popc(mask & ((1u << lane) - 1u))] = idx;
    }
}

// Phase 2: dense march of survivors from k = P1_STEPS+1.
__global__ void __launch_bounds__(256) shadow2_kernel(const float* __restrict__ depth) {
    int total = g_qcount;
    for (int q = blockIdx.x * blockDim.x + threadIdx.x; q < total;
         q += gridDim.x * blockDim.x) {
        int idx = g_queue[q];
        int b = idx >> 16;
        int p = idx & (SS - 1);
        int i = p >> 8;
        int j = p & 255;

        float d = __ldg(depth + b * SS + p);
        const float4* quad = g_quad + b * SS;

        float ci = __fmul_rn(__fadd_rn(__fmul_rn((float)i, 2.0f / 255.0f), -1.0f), T_FOV);
        float cj = __fmul_rn(__fadd_rn(__fmul_rn((float)j, 2.0f / 255.0f), -1.0f), T_FOV);

        float px0 = cj * d, py0 = ci * d;
        const float* prm = g_params + b * 8;
        float sx = -prm[4] * (1.0f / 256.0f);
        float sy = -prm[5] * (1.0f / 256.0f);
        float sz = -prm[6] * (1.0f / 256.0f);
        float minz = __int_as_float(g_min_bits[b]) - 1e-5f;

        float nf = fminf(floorf((d - minz) * __fdividef(-1.0f, sz)), 256.0f);
        int n = (int)nf;

        float sh = 0.0f;
        for (int k = P1_STEPS + 1; k <= n && sh == 0.0f; k += 8) {
            if (march_chunk8(k, nf, d, sx, sy, sz, px0, py0, quad)) sh = 1.0f;
        }
        if (sh != 0.0f) g_shadow[idx] = 1.0f;
    }
}

// Fused: 7x7 separable Gaussian blur of shadow (smem tile) + Phong epilogue.
__global__ void __launch_bounds__(1024) final_kernel(const float* __restrict__ netA,
                                                     const float* __restrict__ normal,
                                                     float* __restrict__ out) {
    __shared__ float s_sh[38][40];
    __shared__ float s_hb[38][33];

    int b = blockIdx.z;
    int ti0 = blockIdx.y * 32;
    int tj0 = blockIdx.x * 32;
    int tx = threadIdx.x;
    int ty = threadIdx.y;
    int tid = ty * 32 + tx;

    const float* shb = g_shadow + b * SS;

    for (int t = tid; t < 38 * 38; t += 1024) {
        int r = t / 38;
        int c = t - r * 38;
        int gi = ti0 - 3 + r;
        int gj = tj0 - 3 + c;
        float v = 0.0f;
        if (gi >= 0 && gi < SDIM && gj >= 0 && gj < SDIM) v = shb[gi * SDIM + gj];
        s_sh[r][c] = v;
    }
    __syncthreads();

    for (int t = tid; t < 38 * 32; t += 1024) {
        int r = t >> 5;
        int c = t & 31;
        float acc = 0.0f;
        #pragma unroll
        for (int dj = 0; dj < 7; dj++) acc += GW[dj] * s_sh[r][c + dj];
        s_hb[r][c] = acc;
    }
    __syncthreads();

    float ssum = 0.0f;
    #pragma unroll
    for (int dy = 0; dy < 7; dy++) ssum += GW[dy] * s_hb[ty + dy][tx];
    float shadow_factor = fminf(fmaxf(1.0f - ssum, 0.1f), 1.0f);

    int i = ti0 + ty;
    int j = tj0 + tx;
    int p = i * SDIM + j;

    const float* prm = g_params + b * 8;
    float la = prm[0], lb = prm[1], spec_alpha = prm[2], spec_strength = prm[3];
    float ldx = prm[4], ldy = prm[5], ldz = prm[6], eps_pow = prm[7];

    const float* nb = normal + b * 3 * SS;
    float nx = __ldg(nb + p);
    float ny = __ldg(nb + SS + p);
    float nz = __ldg(nb + 2 * SS + p);

    float cosb = nx * ldx + ny * ldy + nz * ldz;
    float diffuse = fmaxf(cosb, 0.0f);

    float aj = __fmul_rn(__fadd_rn(__fmul_rn((float)(255 - j), 2.0f / 255.0f), -1.0f), T_FOV);
    float ai = __fmul_rn(__fadd_rn(__fmul_rn((float)(255 - i), 2.0f / 255.0f), -1.0f), T_FOV);
    float rnrm = rsqrtf(ai * ai + aj * aj + 1.0f);
    float vdx = aj * rnrm, vdy = ai * rnrm, vdz = rnrm;

    float rdx = 2.0f * cosb * nx - ldx;
    float rdy = 2.0f * cosb * ny - ldy;
    float rdz = 2.0f * cosb * nz - ldz;

    float mask = (i >= 5 && i < SDIM - 5 && j >= 5 && j < SDIM - 5) ? 1.0f : 0.0f;
    float spec = fmaxf(vdx * rdx + vdy * rdy + vdz * rdz, 0.0f)
               * ((cosb > 0.0f) ? 1.0f : 0.0f) * mask;
    // spec <= EPS clamps to EPS -> spec_sh = EPS^alpha (per-batch constant)
    float spec_sh = (spec > EPSV)
                  ? __powf(fminf(spec, ONE_M_EPS), spec_alpha)
                  : eps_pow;

    float shading = la + lb * diffuse * shadow_factor;
    float term2 = spec_strength * lb * spec_sh;

    const float NLOG2E2 = -2.8853900817779268f;   // -2*log2(e)
    const float* ab = netA + b * 5 * SS;
    float* ob = out + b * 3 * SS;
    #pragma unroll
    for (int c = 0; c < 3; c++) {
        float a = __ldg(ab + c * SS + p);
        float u = exp2f(a * NLOG2E2);
        float alb = exp2f(-GAMMA_F * __log2f(1.0f + u));
        float r = alb * shading + term2;
        ob[c * SS + p] = __powf(fmaxf(r, EPSV), INV_GAMMA);
    }
}

extern "C" void kernel_launch(void* const* d_in, const int* in_sizes, int n_in,
                              void* d_out, int out_size) {
    const float* netA   = (const float*)d_in[0];
    const float* netL   = (const float*)d_in[1];
    const float* normal = (const float*)d_in[2];
    const float* depth  = (const float*)d_in[3];
    const float* light  = (const float*)d_in[4];
    float* out = (float*)d_out;

    params_kernel<<<1, 32>>>(netL, light);
    quad_kernel<<<TOT / 256, 256>>>(depth);
    shadow1_kernel<<<TOT / 256, 256>>>(depth);
    shadow2_kernel<<<1184, 256>>>(depth);   // 8 blocks/SM * 148 SMs
    dim3 grid(SDIM / 32, SDIM / 32, NB);
    dim3 blk(32, 32);
    final_kernel<<<grid, blk>>>(netA, normal, out);
}